// round 7
// baseline (speedup 1.0000x reference)
#include <cuda_runtime.h>
#include <math.h>

#define B_ 32
#define T_ 32
#define F_ 64
#define H_ 256
#define N_ 1024
#define A_ 64
#define C_ 192
#define M_ 256
#define HSOFF (T_*H_*B_)

// ---------------- persistent state (device globals) ----------------
__device__ __align__(16) float g_h[H_*B_];        // h[k*32+b]
__device__ __align__(16) float g_hT[B_*H_];       // h[b*256+k]
__device__ __align__(16) float g_x[T_*F_*B_];     // x[t][f*32+b]
__device__ __align__(16) float g_P[N_*H_];        // P[n*256+k] = addr @ Wq[0:64,:]
__device__ __align__(16) float g_pb[N_];
__device__ __align__(16) float g_candH[T_*B_*C_]; // [(t*32+b)*192+c]
__device__ __align__(16) float g_v[T_*B_*H_];     // [(t*32+b)*256+k]
__device__ float g_cb[T_*B_];                     // [t*32+b]
__device__ float g_d[T_*B_];                      // [s*32+b]
__device__ __align__(16) float g_W1[T_*N_*B_];    // [(s*1024+n)*32+b]
__device__ __align__(16) float g_W2[T_*B_*N_];    // [(s*32+b)*1024+n]
__device__ float g_beta[B_];
__device__ __align__(16) float g_gi[3*H_*B_];     // [row*32+b]
__device__ __align__(16) float g_gh[3*H_*B_];
__device__ __align__(16) float g_sim[N_*B_];      // [n*32+b] (pre-beta)
__device__ __align__(16) float g_r[M_*B_];        // reading [m*32+b]

__device__ __forceinline__ float warp_sum(float v) {
    #pragma unroll
    for (int o = 16; o; o >>= 1) v += __shfl_xor_sync(0xffffffffu, v, o);
    return v;
}
__device__ __forceinline__ float warp_max(float v) {
    #pragma unroll
    for (int o = 16; o; o >>= 1) v = fmaxf(v, __shfl_xor_sync(0xffffffffu, v, o));
    return v;
}

__device__ __forceinline__ void write_out(const float* __restrict__ Wout,
                                          const float* __restrict__ bo,
                                          float* __restrict__ out,
                                          int tstep, int b, int lane) {
    float logit[10];
    float mx = -1e30f;
    #pragma unroll
    for (int o = 0; o < 10; o++) {
        float s = 0.f;
        #pragma unroll
        for (int j = 0; j < 8; j++) {
            int k = lane + 32*j;
            s += Wout[o*H_ + k] * g_h[k*B_ + b];
        }
        s = warp_sum(s);
        s += bo[o];
        logit[o] = s;
        mx = fmaxf(mx, s);
    }
    float se = 0.f;
    #pragma unroll
    for (int o = 0; o < 10; o++) se += expf(logit[o] - mx);
    float lse = mx + logf(se);
    if (lane == 0) {
        #pragma unroll
        for (int o = 0; o < 10; o++)
            out[HSOFF + (tstep*10 + o)*B_ + b] = logit[o] - lse;
    }
}

// ================= K0: init (once) =================
__global__ __launch_bounds__(256, 4)
void k_init(const float* __restrict__ batch, const float* __restrict__ addr,
            const float* __restrict__ Wq, const float* __restrict__ bq)
{
    int tid = threadIdx.x, blk = blockIdx.x;
    int lane = tid & 31, wl = tid >> 5;
    int gt = blk*256 + tid;
    const int GT = 64*256;
    for (int i = gt; i < H_*B_; i += GT) { g_h[i] = 0.f; g_hT[i] = 0.f; }
    for (int i = gt; i < T_*F_*B_; i += GT) {
        int t   = i / (F_*B_);
        int lin = i - t*(F_*B_);
        int bb  = lin >> 6, ff = lin & 63;
        g_x[i] = batch[bb*(T_*F_) + t*F_ + ff];
    }
    int gw = blk*8 + wl;                      // 512 warps
    for (int u = gw; u < N_*8; u += 512) {    // P[n, k0+lane]
        int n = u >> 3, k0 = (u & 7) << 5;
        float acc = 0.f;
        #pragma unroll 8
        for (int a = 0; a < A_; a++) acc += addr[n*A_ + a] * Wq[a*H_ + k0 + lane];
        g_P[n*H_ + k0 + lane] = acc;
    }
    for (int u = gw; u < N_; u += 512) {
        float acc = addr[u*A_ + lane]*bq[lane] + addr[u*A_ + 32 + lane]*bq[32 + lane];
        acc = warp_sum(acc);
        if (lane == 0) g_pb[u] = acc;
    }
}

// ================= KA: gates + d + head(t-1) =================
__global__ __launch_bounds__(1024, 1)
void k_gates(const float* __restrict__ Wi, const float* __restrict__ bi,
             const float* __restrict__ Wh, const float* __restrict__ bh,
             const float* __restrict__ Wch, const float* __restrict__ Wci,
             const float* __restrict__ uvec,
             const float* __restrict__ Wout, const float* __restrict__ bo,
             float* __restrict__ out, int t)
{
    int blk = blockIdx.x, tid = threadIdx.x, lane = tid & 31, wl = tid >> 5;
    __shared__ __align__(16) float smem[10240];
    if (blk < 55) {
        float4* s4 = (float4*)smem;
        const float4* h4 = (const float4*)g_h;
        const float4* x4 = (const float4*)g_x + t*512;
        for (int i = tid; i < 2560; i += 1024) s4[i] = (i < 2048) ? h4[i] : x4[i - 2048];
        __syncthreads();
        int row = blk*32 + wl;
        int b = lane;
        if (row < 768) {                                   // gh
            const float4* w4 = (const float4*)Wh + row*64;
            float acc = bh[row];
            #pragma unroll 8
            for (int kk = 0; kk < 64; kk++) {
                float4 w = w4[kk];
                acc += w.x*smem[(kk*4  )*32 + b] + w.y*smem[(kk*4+1)*32 + b]
                     + w.z*smem[(kk*4+2)*32 + b] + w.w*smem[(kk*4+3)*32 + b];
            }
            g_gh[row*32 + b] = acc;
        } else if (row < 1536) {                           // gi
            int r2 = row - 768;
            const float4* w4 = (const float4*)Wi + r2*16;
            float acc = bi[r2];
            #pragma unroll
            for (int ff = 0; ff < 16; ff++) {
                float4 w = w4[ff];
                acc += w.x*smem[8192 + (ff*4  )*32 + b] + w.y*smem[8192 + (ff*4+1)*32 + b]
                     + w.z*smem[8192 + (ff*4+2)*32 + b] + w.w*smem[8192 + (ff*4+3)*32 + b];
            }
            g_gi[r2*32 + b] = acc;
        } else if (row < 1728) {                           // cand
            int c = row - 1536;
            const float4* wh4 = (const float4*)Wch + c*64;
            const float4* wx4 = (const float4*)Wci + c*16;
            float acc = 0.f;
            #pragma unroll 8
            for (int kk = 0; kk < 64; kk++) {
                float4 w = wh4[kk];
                acc += w.x*smem[(kk*4  )*32 + b] + w.y*smem[(kk*4+1)*32 + b]
                     + w.z*smem[(kk*4+2)*32 + b] + w.w*smem[(kk*4+3)*32 + b];
            }
            #pragma unroll
            for (int ff = 0; ff < 16; ff++) {
                float4 w = wx4[ff];
                acc += w.x*smem[8192 + (ff*4  )*32 + b] + w.y*smem[8192 + (ff*4+1)*32 + b]
                     + w.z*smem[8192 + (ff*4+2)*32 + b] + w.w*smem[8192 + (ff*4+3)*32 + b];
            }
            g_candH[(t*B_ + b)*C_ + c] = fmaxf(acc, 0.f);
        } else if (row == 1728) {                          // beta
            const float4* u4 = (const float4*)uvec;
            float acc = 0.f;
            #pragma unroll 8
            for (int kk = 0; kk < 64; kk++) {
                float4 w = u4[kk];
                acc += w.x*smem[(kk*4  )*32 + b] + w.y*smem[(kk*4+1)*32 + b]
                     + w.z*smem[(kk*4+2)*32 + b] + w.w*smem[(kk*4+3)*32 + b];
            }
            float sp = (acc > 0.f) ? acc + log1pf(expf(-acc)) : log1pf(expf(acc));
            g_beta[b] = sp + 1.f;
        }
    } else if (blk < 86) {
        int idx = (blk - 55)*32 + wl;                      // d_s[b], s<t
        if (idx < 32*t) {
            int s = idx >> 5, b = idx & 31;
            const float* vr = g_v + (s*B_ + b)*H_;
            const float* hb = g_hT + b*H_;
            float acc = 0.f;
            #pragma unroll
            for (int j = 0; j < 8; j++) acc += vr[lane + 32*j] * hb[lane + 32*j];
            acc = warp_sum(acc);
            if (lane == 0) g_d[s*32 + b] = acc + g_cb[s*32 + b];
        }
    } else {
        if (t > 0) write_out(Wout, bo, out, t - 1, wl, lane);
    }
}

// ================= KB: sim[n,b] =================
__global__ __launch_bounds__(512, 1)
void k_sim(int t)
{
    __shared__ __align__(16) float s_h[8192];
    __shared__ float s_d[1024];
    int tid = threadIdx.x, lane = tid & 31, wl = tid >> 5, blk = blockIdx.x;
    float4* sh4 = (float4*)s_h;
    const float4* h4 = (const float4*)g_h;
    for (int i = tid; i < 2048; i += 512) sh4[i] = h4[i];
    for (int i = tid; i < 32*t; i += 512) s_d[i] = g_d[i];
    __syncthreads();

    int n = blk*16 + wl;
    float preg[8];
    #pragma unroll
    for (int j = 0; j < 8; j++) preg[j] = g_P[n*H_ + j*32 + lane];
    float acc = g_pb[n];
    #pragma unroll
    for (int j = 0; j < 8; j++) {
        #pragma unroll
        for (int kk = 0; kk < 32; kk++) {
            float pk = __shfl_sync(0xffffffffu, preg[j], kk);
            acc += pk * s_h[(j*32 + kk)*32 + lane];
        }
    }
    for (int s = 0; s < t; s++)
        acc += g_W1[(s*N_ + n)*32 + lane] * s_d[s*32 + lane];
    g_sim[n*32 + lane] = acc;
}

// ================= KC: softmax + w + G + reading =================
__global__ __launch_bounds__(256, 1)
void k_soft(const float* __restrict__ addr, int t)
{
    __shared__ __align__(16) float s_w[1024];
    __shared__ float s_G[32];
    __shared__ float s_red[64];
    __shared__ float s_m[8];
    int b = blockIdx.x, tid = threadIdx.x, lane = tid & 31, wl = tid >> 5;
    float bs = g_beta[b];
    float v0 = bs * g_sim[(tid      )*32 + b];
    float v1 = bs * g_sim[(tid + 256)*32 + b];
    float v2 = bs * g_sim[(tid + 512)*32 + b];
    float v3 = bs * g_sim[(tid + 768)*32 + b];
    float m = fmaxf(fmaxf(v0, v1), fmaxf(v2, v3));
    m = warp_max(m);
    if (lane == 0) s_m[wl] = m;
    __syncthreads();
    float mb = s_m[0];
    #pragma unroll
    for (int w = 1; w < 8; w++) mb = fmaxf(mb, s_m[w]);
    float e = expf(v0 - mb) + expf(v1 - mb) + expf(v2 - mb) + expf(v3 - mb);
    e = warp_sum(e);
    __syncthreads();
    if (lane == 0) s_m[wl] = e;
    __syncthreads();
    float ss = 0.f;
    #pragma unroll
    for (int w = 0; w < 8; w++) ss += s_m[w];
    float li = 1.f / ss;

    float ws0 = expf(v0 - mb) * li;
    float ws1 = expf(v1 - mb) * li;
    float ws2 = expf(v2 - mb) * li;
    float ws3 = expf(v3 - mb) * li;
    s_w[tid      ] = ws0;  s_w[tid + 256] = ws1;
    s_w[tid + 512] = ws2;  s_w[tid + 768] = ws3;
    g_W1[(t*N_ + tid      )*32 + b] = ws0;
    g_W1[(t*N_ + tid + 256)*32 + b] = ws1;
    g_W1[(t*N_ + tid + 512)*32 + b] = ws2;
    g_W1[(t*N_ + tid + 768)*32 + b] = ws3;
    float* w2row = g_W2 + (t*B_ + b)*N_;
    w2row[tid] = ws0; w2row[tid+256] = ws1; w2row[tid+512] = ws2; w2row[tid+768] = ws3;
    if (tid < 64) s_red[tid] = 0.f;
    __syncthreads();

    // G_s = w_t . w_s (warp per s)
    for (int s = wl; s < t; s += 8) {
        const float4* w2 = (const float4*)(g_W2 + (s*B_ + b)*N_);
        const float4* sw4 = (const float4*)s_w;
        float g = 0.f;
        #pragma unroll
        for (int j = 0; j < 8; j++) {
            float4 a_ = w2[j*32 + lane];
            float4 c_ = sw4[j*32 + lane];
            g += a_.x*c_.x + a_.y*c_.y + a_.z*c_.z + a_.w*c_.w;
        }
        g = warp_sum(g);
        if (lane == 0) s_G[s] = g;
    }
    // ra partial (warp over 128 n's, lanes = a)
    float a0 = 0.f, a1 = 0.f;
    #pragma unroll 4
    for (int i = 0; i < 128; i++) {
        int n = wl*128 + i;
        float wv = s_w[n];
        a0 += wv * addr[n*A_ + lane];
        a1 += wv * addr[n*A_ + 32 + lane];
    }
    atomicAdd(&s_red[lane], a0);
    atomicAdd(&s_red[lane + 32], a1);
    __syncthreads();
    if (tid < 64) g_r[tid*32 + b] = s_red[tid];
    // rc[c] = sum_s G_s * cand_s[c,b]
    if (tid < C_) {
        float acc = 0.f;
        for (int s = 0; s < t; s++)
            acc += s_G[s] * g_candH[(s*B_ + b)*C_ + tid];
        g_r[(A_ + tid)*32 + b] = acc;
    }
}

// ================= KD: GRU + v_t + cb_t =================
__global__ __launch_bounds__(1024, 1)
void k_gru(const float* __restrict__ Wm, const float* __restrict__ bm,
           const float* __restrict__ Wq, const float* __restrict__ bq,
           float* __restrict__ out, int t)
{
    int blk = blockIdx.x, tid = threadIdx.x, lane = tid & 31, wl = tid >> 5;
    __shared__ __align__(16) float smem[10240];
    if (blk < 16) {
        float4* s4 = (float4*)smem;
        const float4* r4 = (const float4*)g_r;
        for (int i = tid; i < 2048; i += 1024) s4[i] = r4[i];
        __syncthreads();
        int p = wl >> 1, kh = wl & 1;
        int hid = blk*16 + p, b = lane;
        const float4* wm4 = (const float4*)Wm;
        float acc0, acc1, acc2;
        if (kh == 0) { acc0 = bm[hid]; acc1 = bm[H_ + hid]; acc2 = bm[2*H_ + hid]; }
        else { acc0 = acc1 = acc2 = 0.f; }
        int mbeg = kh << 5;
        #pragma unroll 4
        for (int mm = mbeg; mm < mbeg + 32; mm++) {
            float r0 = smem[(mm*4  )*32 + b], r1 = smem[(mm*4+1)*32 + b];
            float r2 = smem[(mm*4+2)*32 + b], r3 = smem[(mm*4+3)*32 + b];
            float4 w0 = wm4[hid*64 + mm];
            float4 w1 = wm4[(H_ + hid)*64 + mm];
            float4 w2 = wm4[(2*H_ + hid)*64 + mm];
            acc0 += w0.x*r0 + w0.y*r1 + w0.z*r2 + w0.w*r3;
            acc1 += w1.x*r0 + w1.y*r1 + w1.z*r2 + w1.w*r3;
            acc2 += w2.x*r0 + w2.y*r1 + w2.z*r2 + w2.w*r3;
        }
        float* s_c = smem + 8192;
        if (kh == 1) {
            s_c[(p*3    )*32 + b] = acc0;
            s_c[(p*3 + 1)*32 + b] = acc1;
            s_c[(p*3 + 2)*32 + b] = acc2;
        }
        __syncthreads();
        if (kh == 0) {
            acc0 += s_c[(p*3    )*32 + b];
            acc1 += s_c[(p*3 + 1)*32 + b];
            acc2 += s_c[(p*3 + 2)*32 + b];
            int gb = hid*32 + b;
            float r  = 1.f / (1.f + expf(-(g_gi[gb] + g_gh[gb] + acc0)));
            float z  = 1.f / (1.f + expf(-(g_gi[H_*B_ + gb] + g_gh[H_*B_ + gb] + acc1)));
            float nn = tanhf(g_gi[2*H_*B_ + gb] + acc2 + r * g_gh[2*H_*B_ + gb]);
            float hn = (1.f - z)*nn + z*g_h[gb];
            g_h[gb] = hn;
            g_hT[b*H_ + hid] = hn;
            out[t*H_*B_ + gb] = hn;
        }
    } else if (blk < 20) {
        // v_t for 8 b's
        int b0v = (blk - 16)*8;
        float4* s4 = (float4*)smem;
        const float4* c4 = (const float4*)(g_candH + (t*B_ + b0v)*C_);
        for (int i = tid; i < 384; i += 1024) s4[i] = c4[i];   // s_c[bl*192+c]
        __syncthreads();
        int bl = wl >> 2, b = b0v + bl;
        int kh = (wl >> 1) & 1, ch = wl & 1;
        float a0 = 0.f, a1 = 0.f, a2 = 0.f, a3 = 0.f;
        const float4* wq4 = (const float4*)Wq;
        int cbeg = ch*96;
        #pragma unroll 4
        for (int c = cbeg; c < cbeg + 96; c++) {
            float4 w = wq4[(A_ + c)*64 + kh*32 + lane];
            float cv = smem[bl*C_ + c];
            a0 += w.x*cv; a1 += w.y*cv; a2 += w.z*cv; a3 += w.w*cv;
        }
        float* s_v = smem + 2048;
        int pidx = wl >> 1;
        if (ch == 1) {
            s_v[pidx*128 + lane*4    ] = a0;
            s_v[pidx*128 + lane*4 + 1] = a1;
            s_v[pidx*128 + lane*4 + 2] = a2;
            s_v[pidx*128 + lane*4 + 3] = a3;
        }
        __syncthreads();
        if (ch == 0) {
            a0 += s_v[pidx*128 + lane*4    ];
            a1 += s_v[pidx*128 + lane*4 + 1];
            a2 += s_v[pidx*128 + lane*4 + 2];
            a3 += s_v[pidx*128 + lane*4 + 3];
            ((float4*)g_v)[(t*B_ + b)*64 + kh*32 + lane] = make_float4(a0, a1, a2, a3);
        }
    } else {
        // cb_t[b]
        int b = wl;
        float acc = 0.f;
        #pragma unroll
        for (int j = 0; j < 6; j++) {
            int c = lane + 32*j;
            acc += g_candH[(t*B_ + b)*C_ + c] * bq[A_ + c];
        }
        acc = warp_sum(acc);
        if (lane == 0) g_cb[t*32 + b] = acc;
    }
}

// ================= KH: final head =================
__global__ __launch_bounds__(1024, 1)
void k_head(const float* __restrict__ Wout, const float* __restrict__ bo,
            float* __restrict__ out)
{
    int lane = threadIdx.x & 31, wl = threadIdx.x >> 5;
    write_out(Wout, bo, out, T_ - 1, wl, lane);
}

extern "C" void kernel_launch(void* const* d_in, const int* in_sizes, int n_in,
                              void* d_out, int out_size) {
    (void)in_sizes; (void)n_in; (void)out_size;
    const float* batch = (const float*)d_in[0];
    const float* Wi    = (const float*)d_in[1];
    const float* bi    = (const float*)d_in[2];
    const float* Wh    = (const float*)d_in[3];
    const float* bh    = (const float*)d_in[4];
    const float* Wm    = (const float*)d_in[5];
    const float* bm    = (const float*)d_in[6];
    const float* Wout  = (const float*)d_in[7];
    const float* bo    = (const float*)d_in[8];
    const float* addr  = (const float*)d_in[9];
    const float* Wq    = (const float*)d_in[10];
    const float* bq    = (const float*)d_in[11];
    const float* u     = (const float*)d_in[12];
    const float* Wch   = (const float*)d_in[13];
    const float* Wci   = (const float*)d_in[14];
    float* out = (float*)d_out;

    k_init<<<64, 256>>>(batch, addr, Wq, bq);
    for (int t = 0; t < T_; t++) {
        k_gates<<<87, 1024>>>(Wi, bi, Wh, bh, Wch, Wci, u, Wout, bo, out, t);
        k_sim<<<64, 512>>>(t);
        k_soft<<<32, 256>>>(addr, t);
        k_gru<<<21, 1024>>>(Wm, bm, Wq, bq, out, t);
    }
    k_head<<<1, 1024>>>(Wout, bo, out);
}

// round 8
// speedup vs baseline: 1.1897x; 1.1897x over previous
#include <cuda_runtime.h>
#include <math.h>

#define B_ 32
#define T_ 32
#define F_ 64
#define H_ 256
#define N_ 1024
#define A_ 64
#define C_ 192
#define M_ 256
#define HSOFF (T_*H_*B_)

// ---------------- persistent state (device globals) ----------------
__device__ __align__(16) float g_h[H_*B_];        // h[k*32+b]
__device__ __align__(16) float g_hT[B_*H_];       // h[b*256+k]
__device__ __align__(16) float g_x[T_*F_*B_];     // x[t][f*32+b]
__device__ __align__(16) float g_qT[B_*M_];       // q[b*256+m] (incl. bias)
__device__ __align__(16) float g_candH[T_*B_*C_]; // [(t*32+b)*192+c]
__device__ float g_d[T_*B_];                      // [s*32+b]
__device__ __align__(16) float g_W1[T_*N_*B_];    // [(s*1024+n)*32+b]
__device__ __align__(16) float g_W2[T_*B_*N_];    // [(s*32+b)*1024+n]
__device__ float g_beta[B_];
__device__ __align__(16) float g_gi[3*H_*B_];     // [row*32+b]
__device__ __align__(16) float g_gh[3*H_*B_];
__device__ __align__(16) float g_simT[B_*N_];     // [b*1024+n]
__device__ __align__(16) float g_r[M_*B_];        // reading [m*32+b]

__device__ __forceinline__ float warp_sum(float v) {
    #pragma unroll
    for (int o = 16; o; o >>= 1) v += __shfl_xor_sync(0xffffffffu, v, o);
    return v;
}
__device__ __forceinline__ float warp_max(float v) {
    #pragma unroll
    for (int o = 16; o; o >>= 1) v = fmaxf(v, __shfl_xor_sync(0xffffffffu, v, o));
    return v;
}

__device__ __forceinline__ void write_out(const float* __restrict__ Wout,
                                          const float* __restrict__ bo,
                                          float* __restrict__ out,
                                          int tstep, int b, int lane) {
    float logit[10];
    float mx = -1e30f;
    #pragma unroll
    for (int o = 0; o < 10; o++) {
        float s = 0.f;
        #pragma unroll
        for (int j = 0; j < 8; j++) {
            int k = lane + 32*j;
            s += Wout[o*H_ + k] * g_h[k*B_ + b];
        }
        s = warp_sum(s);
        s += bo[o];
        logit[o] = s;
        mx = fmaxf(mx, s);
    }
    float se = 0.f;
    #pragma unroll
    for (int o = 0; o < 10; o++) se += expf(logit[o] - mx);
    float lse = mx + logf(se);
    if (lane == 0) {
        #pragma unroll
        for (int o = 0; o < 10; o++)
            out[HSOFF + (tstep*10 + o)*B_ + b] = logit[o] - lse;
    }
}

// ================= K0: init (once) =================
__global__ __launch_bounds__(256, 4)
void k_init(const float* __restrict__ batch)
{
    int gt = blockIdx.x*256 + threadIdx.x;
    const int GT = 32*256;
    for (int i = gt; i < H_*B_; i += GT) { g_h[i] = 0.f; g_hT[i] = 0.f; }
    for (int i = gt; i < T_*F_*B_; i += GT) {
        int t   = i / (F_*B_);
        int lin = i - t*(F_*B_);
        int bb  = lin >> 6, ff = lin & 63;
        g_x[i] = batch[bb*(T_*F_) + t*F_ + ff];
    }
}

// ================= KA: gates + q + d + head(t-1) =================
__global__ __launch_bounds__(1024, 1)
void k_gates(const float* __restrict__ Wi, const float* __restrict__ bi,
             const float* __restrict__ Wh, const float* __restrict__ bh,
             const float* __restrict__ Wch, const float* __restrict__ Wci,
             const float* __restrict__ uvec,
             const float* __restrict__ Wq, const float* __restrict__ bq,
             const float* __restrict__ Wout, const float* __restrict__ bo,
             float* __restrict__ out, int t)
{
    int blk = blockIdx.x, tid = threadIdx.x, lane = tid & 31, wl = tid >> 5;
    __shared__ __align__(16) float smem[10240];
    if (blk < 55) {
        // ---- gate rows: stage h (8192) + x_t (2048) ----
        float4* s4 = (float4*)smem;
        const float4* h4 = (const float4*)g_h;
        const float4* x4 = (const float4*)g_x + t*512;
        for (int i = tid; i < 2560; i += 1024) s4[i] = (i < 2048) ? h4[i] : x4[i - 2048];
        __syncthreads();
        int row = blk*32 + wl;
        int b = lane;
        if (row < 768) {                                   // gh
            const float4* w4 = (const float4*)Wh + row*64;
            float acc = bh[row];
            #pragma unroll 8
            for (int kk = 0; kk < 64; kk++) {
                float4 w = w4[kk];
                acc += w.x*smem[(kk*4  )*32 + b] + w.y*smem[(kk*4+1)*32 + b]
                     + w.z*smem[(kk*4+2)*32 + b] + w.w*smem[(kk*4+3)*32 + b];
            }
            g_gh[row*32 + b] = acc;
        } else if (row < 1536) {                           // gi
            int r2 = row - 768;
            const float4* w4 = (const float4*)Wi + r2*16;
            float acc = bi[r2];
            #pragma unroll
            for (int ff = 0; ff < 16; ff++) {
                float4 w = w4[ff];
                acc += w.x*smem[8192 + (ff*4  )*32 + b] + w.y*smem[8192 + (ff*4+1)*32 + b]
                     + w.z*smem[8192 + (ff*4+2)*32 + b] + w.w*smem[8192 + (ff*4+3)*32 + b];
            }
            g_gi[r2*32 + b] = acc;
        } else if (row < 1728) {                           // cand
            int c = row - 1536;
            const float4* wh4 = (const float4*)Wch + c*64;
            const float4* wx4 = (const float4*)Wci + c*16;
            float acc = 0.f;
            #pragma unroll 8
            for (int kk = 0; kk < 64; kk++) {
                float4 w = wh4[kk];
                acc += w.x*smem[(kk*4  )*32 + b] + w.y*smem[(kk*4+1)*32 + b]
                     + w.z*smem[(kk*4+2)*32 + b] + w.w*smem[(kk*4+3)*32 + b];
            }
            #pragma unroll
            for (int ff = 0; ff < 16; ff++) {
                float4 w = wx4[ff];
                acc += w.x*smem[8192 + (ff*4  )*32 + b] + w.y*smem[8192 + (ff*4+1)*32 + b]
                     + w.z*smem[8192 + (ff*4+2)*32 + b] + w.w*smem[8192 + (ff*4+3)*32 + b];
            }
            g_candH[(t*B_ + b)*C_ + c] = fmaxf(acc, 0.f);
        } else if (row == 1728) {                          // beta
            const float4* u4 = (const float4*)uvec;
            float acc = 0.f;
            #pragma unroll 8
            for (int kk = 0; kk < 64; kk++) {
                float4 w = u4[kk];
                acc += w.x*smem[(kk*4  )*32 + b] + w.y*smem[(kk*4+1)*32 + b]
                     + w.z*smem[(kk*4+2)*32 + b] + w.w*smem[(kk*4+3)*32 + b];
            }
            float sp = (acc > 0.f) ? acc + log1pf(expf(-acc)) : log1pf(expf(acc));
            g_beta[b] = sp + 1.f;
        }
    } else if (blk < 87) {
        // ---- per-b block: q[·,b] = Wq h_b + bq, then d_s[b] = cand_s . q_c ----
        int b = blk - 55;
        if (tid < 256) smem[tid] = g_hT[b*H_ + tid];       // s_h[256]
        __syncthreads();
        float* s_q = smem + 256;
        const float4* sh4 = (const float4*)smem;
        // 32 warps x 8 rows
        #pragma unroll
        for (int rr = 0; rr < 8; rr++) {
            int m = wl*8 + rr;
            const float4* wrow = (const float4*)(Wq + m*H_);
            float4 w1 = wrow[lane], w2 = wrow[32 + lane];
            float4 h1 = sh4[lane],  h2 = sh4[32 + lane];
            float acc = w1.x*h1.x + w1.y*h1.y + w1.z*h1.z + w1.w*h1.w
                      + w2.x*h2.x + w2.y*h2.y + w2.z*h2.z + w2.w*h2.w;
            acc = warp_sum(acc);
            if (lane == 0) {
                acc += bq[m];
                s_q[m] = acc;
                g_qT[b*M_ + m] = acc;
            }
        }
        __syncthreads();
        if (wl < t) {                                      // d_s, s = wl < t <= 31
            const float* cr = g_candH + (wl*B_ + b)*C_;
            float acc = 0.f;
            #pragma unroll
            for (int j = 0; j < 6; j++)
                acc += cr[lane + 32*j] * s_q[A_ + lane + 32*j];
            acc = warp_sum(acc);
            if (lane == 0) g_d[wl*32 + b] = acc;
        }
    } else {
        if (t > 0) write_out(Wout, bo, out, t - 1, wl, lane);
    }
}

// ================= KB: sim -> simT[b][n] =================
__global__ __launch_bounds__(512, 2)
void k_sim(const float* __restrict__ addr, int t)
{
    __shared__ __align__(16) float s_qa[A_*B_];    // [a*32+b]
    __shared__ __align__(16) float s_a[16*A_];     // addr rows for this block
    __shared__ float s_d[T_*B_];
    __shared__ float s_t[B_*17];
    int tid = threadIdx.x, lane = tid & 31, wl = tid >> 5, blk = blockIdx.x;
    for (int i = tid; i < 2048; i += 512) {
        int bb = i >> 6, aa = i & 63;
        s_qa[aa*32 + bb] = g_qT[bb*M_ + aa];
    }
    for (int i = tid; i < 1024; i += 512) s_a[i] = addr[blk*1024 + i];
    for (int i = tid; i < 32*t; i += 512) s_d[i] = g_d[i];
    __syncthreads();

    int n = blk*16 + wl;                            // warp per n, lane = b
    const float4* a4 = (const float4*)(s_a + wl*A_);
    float acc = 0.f;
    #pragma unroll
    for (int j = 0; j < 16; j++) {
        float4 av = a4[j];                          // uniform broadcast LDS.128
        acc += av.x*s_qa[(4*j  )*32 + lane] + av.y*s_qa[(4*j+1)*32 + lane]
             + av.z*s_qa[(4*j+2)*32 + lane] + av.w*s_qa[(4*j+3)*32 + lane];
    }
    for (int s = 0; s < t; s++)
        acc += g_W1[(s*N_ + n)*32 + lane] * s_d[s*32 + lane];
    s_t[lane*17 + wl] = acc;
    __syncthreads();
    {   // coalesced transpose write
        int b = tid >> 4, nl = tid & 15;
        g_simT[b*N_ + blk*16 + nl] = s_t[b*17 + nl];
    }
}

// ================= KC: softmax + w + G + reading =================
__global__ __launch_bounds__(1024, 1)
void k_soft(const float* __restrict__ addr, int t)
{
    __shared__ __align__(16) float s_w[N_];
    __shared__ float s_G[32];
    __shared__ float s_red[64];
    __shared__ float s_m[32];
    int b = blockIdx.x, tid = threadIdx.x, lane = tid & 31, wl = tid >> 5;
    float bs = g_beta[b];
    float v = bs * g_simT[b*N_ + tid];              // coalesced
    float m = warp_max(v);
    if (lane == 0) s_m[wl] = m;
    __syncthreads();
    float mb = s_m[0];
    #pragma unroll
    for (int w = 1; w < 32; w++) mb = fmaxf(mb, s_m[w]);
    float e = expf(v - mb);
    float es = warp_sum(e);
    __syncthreads();
    if (lane == 0) s_m[wl] = es;
    __syncthreads();
    float ss = 0.f;
    #pragma unroll
    for (int w = 0; w < 32; w++) ss += s_m[w];
    float wv = e / ss;
    s_w[tid] = wv;
    g_W1[(t*N_ + tid)*32 + b] = wv;                 // scattered store (cheap)
    g_W2[(t*B_ + b)*N_ + tid] = wv;                 // coalesced
    if (tid < 64) s_red[tid] = 0.f;
    __syncthreads();

    // G_s = w_t . w_s  (warp per s)
    if (wl < t) {
        const float4* w2 = (const float4*)(g_W2 + (wl*B_ + b)*N_);
        const float4* sw4 = (const float4*)s_w;
        float g = 0.f;
        #pragma unroll
        for (int j = 0; j < 8; j++) {
            float4 a_ = w2[j*32 + lane];
            float4 c_ = sw4[j*32 + lane];
            g += a_.x*c_.x + a_.y*c_.y + a_.z*c_.z + a_.w*c_.w;
        }
        g = warp_sum(g);
        if (lane == 0) s_G[wl] = g;
    }
    // ra: warp w handles n in [w*32, w*32+32)
    {
        float a0 = 0.f, a1 = 0.f;
        #pragma unroll 4
        for (int i = 0; i < 32; i++) {
            int n = wl*32 + i;
            float wn = s_w[n];
            a0 += wn * addr[n*A_ + lane];
            a1 += wn * addr[n*A_ + 32 + lane];
        }
        atomicAdd(&s_red[lane], a0);
        atomicAdd(&s_red[lane + 32], a1);
    }
    __syncthreads();
    if (tid < 64) g_r[tid*32 + b] = s_red[tid];
    // rc[c] = sum_s G_s * cand_s[c,b]
    if (tid < C_) {
        float acc = 0.f;
        for (int s = 0; s < t; s++)
            acc += s_G[s] * g_candH[(s*B_ + b)*C_ + tid];
        g_r[(A_ + tid)*32 + b] = acc;
    }
}

// ================= KD: GRU =================
__global__ __launch_bounds__(1024, 1)
void k_gru(const float* __restrict__ Wm, const float* __restrict__ bm,
           float* __restrict__ out, int t)
{
    int blk = blockIdx.x, tid = threadIdx.x, lane = tid & 31, wl = tid >> 5;
    __shared__ __align__(16) float smem[10240];
    float4* s4 = (float4*)smem;
    const float4* r4 = (const float4*)g_r;
    for (int i = tid; i < 2048; i += 1024) s4[i] = r4[i];
    __syncthreads();
    int p = wl >> 1, kh = wl & 1;
    int hid = blk*16 + p, b = lane;
    const float4* wm4 = (const float4*)Wm;
    float acc0, acc1, acc2;
    if (kh == 0) { acc0 = bm[hid]; acc1 = bm[H_ + hid]; acc2 = bm[2*H_ + hid]; }
    else { acc0 = acc1 = acc2 = 0.f; }
    int mbeg = kh << 5;
    #pragma unroll 4
    for (int mm = mbeg; mm < mbeg + 32; mm++) {
        float r0 = smem[(mm*4  )*32 + b], r1 = smem[(mm*4+1)*32 + b];
        float r2 = smem[(mm*4+2)*32 + b], r3 = smem[(mm*4+3)*32 + b];
        float4 w0 = wm4[hid*64 + mm];
        float4 w1 = wm4[(H_ + hid)*64 + mm];
        float4 w2 = wm4[(2*H_ + hid)*64 + mm];
        acc0 += w0.x*r0 + w0.y*r1 + w0.z*r2 + w0.w*r3;
        acc1 += w1.x*r0 + w1.y*r1 + w1.z*r2 + w1.w*r3;
        acc2 += w2.x*r0 + w2.y*r1 + w2.z*r2 + w2.w*r3;
    }
    float* s_c = smem + 8192;
    if (kh == 1) {
        s_c[(p*3    )*32 + b] = acc0;
        s_c[(p*3 + 1)*32 + b] = acc1;
        s_c[(p*3 + 2)*32 + b] = acc2;
    }
    __syncthreads();
    if (kh == 0) {
        acc0 += s_c[(p*3    )*32 + b];
        acc1 += s_c[(p*3 + 1)*32 + b];
        acc2 += s_c[(p*3 + 2)*32 + b];
        int gb = hid*32 + b;
        float r  = 1.f / (1.f + expf(-(g_gi[gb] + g_gh[gb] + acc0)));
        float z  = 1.f / (1.f + expf(-(g_gi[H_*B_ + gb] + g_gh[H_*B_ + gb] + acc1)));
        float nn = tanhf(g_gi[2*H_*B_ + gb] + acc2 + r * g_gh[2*H_*B_ + gb]);
        float hn = (1.f - z)*nn + z*g_h[gb];
        g_h[gb] = hn;
        g_hT[b*H_ + hid] = hn;
        out[t*H_*B_ + gb] = hn;
    }
}

// ================= KH: final head =================
__global__ __launch_bounds__(1024, 1)
void k_head(const float* __restrict__ Wout, const float* __restrict__ bo,
            float* __restrict__ out)
{
    int lane = threadIdx.x & 31, wl = threadIdx.x >> 5;
    write_out(Wout, bo, out, T_ - 1, wl, lane);
}

extern "C" void kernel_launch(void* const* d_in, const int* in_sizes, int n_in,
                              void* d_out, int out_size) {
    (void)in_sizes; (void)n_in; (void)out_size;
    const float* batch = (const float*)d_in[0];
    const float* Wi    = (const float*)d_in[1];
    const float* bi    = (const float*)d_in[2];
    const float* Wh    = (const float*)d_in[3];
    const float* bh    = (const float*)d_in[4];
    const float* Wm    = (const float*)d_in[5];
    const float* bm    = (const float*)d_in[6];
    const float* Wout  = (const float*)d_in[7];
    const float* bo    = (const float*)d_in[8];
    const float* addr  = (const float*)d_in[9];
    const float* Wq    = (const float*)d_in[10];
    const float* bq    = (const float*)d_in[11];
    const float* u     = (const float*)d_in[12];
    const float* Wch   = (const float*)d_in[13];
    const float* Wci   = (const float*)d_in[14];
    float* out = (float*)d_out;

    k_init<<<32, 256>>>(batch);
    for (int t = 0; t < T_; t++) {
        k_gates<<<88, 1024>>>(Wi, bi, Wh, bh, Wch, Wci, u, Wq, bq, Wout, bo, out, t);
        k_sim<<<64, 512>>>(addr, t);
        k_soft<<<32, 1024>>>(addr, t);
        k_gru<<<16, 1024>>>(Wm, bm, out, t);
    }
    k_head<<<1, 1024>>>(Wout, bo, out);
}

// round 9
// speedup vs baseline: 1.2907x; 1.0849x over previous
#include <cuda_runtime.h>
#include <math.h>

#define B_ 32
#define T_ 32
#define F_ 64
#define H_ 256
#define N_ 1024
#define A_ 64
#define C_ 192
#define M_ 256
#define HSOFF (T_*H_*B_)

// ---------------- persistent state (device globals) ----------------
__device__ __align__(16) float g_h[H_*B_];        // h[k*32+b]
__device__ __align__(16) float g_x[T_*F_*B_];     // x[t][f*32+b]
__device__ __align__(16) float g_addrT[A_*N_];    // addrT[a*1024+n]
__device__ __align__(16) float g_q[B_*M_];        // q[b*256+m] (incl. bias)
__device__ __align__(16) float g_candH[T_*B_*C_]; // [(t*32+b)*192+c]
__device__ __align__(16) float g_W2[T_*B_*N_];    // w_s: [(s*32+b)*1024+n]
__device__ float g_beta[B_];
__device__ __align__(16) float g_gi[3*H_*B_];     // [row*32+b]
__device__ __align__(16) float g_gh[3*H_*B_];
__device__ __align__(16) float g_r[M_*B_];        // reading [m*32+b]

__device__ __forceinline__ float warp_sum(float v) {
    #pragma unroll
    for (int o = 16; o; o >>= 1) v += __shfl_xor_sync(0xffffffffu, v, o);
    return v;
}
__device__ __forceinline__ float warp_max(float v) {
    #pragma unroll
    for (int o = 16; o; o >>= 1) v = fmaxf(v, __shfl_xor_sync(0xffffffffu, v, o));
    return v;
}

__device__ __forceinline__ void write_out(const float* __restrict__ Wout,
                                          const float* __restrict__ bo,
                                          float* __restrict__ out,
                                          int tstep, int b, int lane) {
    float logit[10];
    float mx = -1e30f;
    #pragma unroll
    for (int o = 0; o < 10; o++) {
        float s = 0.f;
        #pragma unroll
        for (int j = 0; j < 8; j++) {
            int k = lane + 32*j;
            s += Wout[o*H_ + k] * g_h[k*B_ + b];
        }
        s = warp_sum(s);
        s += bo[o];
        logit[o] = s;
        mx = fmaxf(mx, s);
    }
    float se = 0.f;
    #pragma unroll
    for (int o = 0; o < 10; o++) se += expf(logit[o] - mx);
    float lse = mx + logf(se);
    if (lane == 0) {
        #pragma unroll
        for (int o = 0; o < 10; o++)
            out[HSOFF + (tstep*10 + o)*B_ + b] = logit[o] - lse;
    }
}

// ================= K0: init (once) =================
__global__ __launch_bounds__(256, 4)
void k_init(const float* __restrict__ batch, const float* __restrict__ addr)
{
    int gt = blockIdx.x*256 + threadIdx.x;
    const int GT = 64*256;
    for (int i = gt; i < H_*B_; i += GT) g_h[i] = 0.f;
    for (int i = gt; i < T_*F_*B_; i += GT) {
        int t   = i / (F_*B_);
        int lin = i - t*(F_*B_);
        int bb  = lin >> 6, ff = lin & 63;
        g_x[i] = batch[bb*(T_*F_) + t*F_ + ff];
    }
    for (int i = gt; i < A_*N_; i += GT) {
        int a = i >> 10, n = i & 1023;
        g_addrT[i] = addr[n*A_ + a];
    }
}

// ================= K1: gates + q + head(t-1) =================
__global__ __launch_bounds__(1024, 1)
void k_front(const float* __restrict__ Wi, const float* __restrict__ bi,
             const float* __restrict__ Wh, const float* __restrict__ bh,
             const float* __restrict__ Wch, const float* __restrict__ Wci,
             const float* __restrict__ uvec,
             const float* __restrict__ Wq, const float* __restrict__ bq,
             const float* __restrict__ Wout, const float* __restrict__ bo,
             float* __restrict__ out, int t)
{
    int blk = blockIdx.x, tid = threadIdx.x, lane = tid & 31, wl = tid >> 5;
    __shared__ __align__(16) float smem[10240];
    if (blk < 55) {
        // ---- gate rows: stage h (8192) + x_t (2048) ----
        float4* s4 = (float4*)smem;
        const float4* h4 = (const float4*)g_h;
        const float4* x4 = (const float4*)g_x + t*512;
        for (int i = tid; i < 2560; i += 1024) s4[i] = (i < 2048) ? h4[i] : x4[i - 2048];
        __syncthreads();
        int row = blk*32 + wl;
        int b = lane;
        if (row < 768) {                                   // gh
            const float4* w4 = (const float4*)Wh + row*64;
            float acc = bh[row];
            #pragma unroll 8
            for (int kk = 0; kk < 64; kk++) {
                float4 w = w4[kk];
                acc += w.x*smem[(kk*4  )*32 + b] + w.y*smem[(kk*4+1)*32 + b]
                     + w.z*smem[(kk*4+2)*32 + b] + w.w*smem[(kk*4+3)*32 + b];
            }
            g_gh[row*32 + b] = acc;
        } else if (row < 1536) {                           // gi
            int r2 = row - 768;
            const float4* w4 = (const float4*)Wi + r2*16;
            float acc = bi[r2];
            #pragma unroll
            for (int ff = 0; ff < 16; ff++) {
                float4 w = w4[ff];
                acc += w.x*smem[8192 + (ff*4  )*32 + b] + w.y*smem[8192 + (ff*4+1)*32 + b]
                     + w.z*smem[8192 + (ff*4+2)*32 + b] + w.w*smem[8192 + (ff*4+3)*32 + b];
            }
            g_gi[r2*32 + b] = acc;
        } else if (row < 1728) {                           // cand
            int c = row - 1536;
            const float4* wh4 = (const float4*)Wch + c*64;
            const float4* wx4 = (const float4*)Wci + c*16;
            float acc = 0.f;
            #pragma unroll 8
            for (int kk = 0; kk < 64; kk++) {
                float4 w = wh4[kk];
                acc += w.x*smem[(kk*4  )*32 + b] + w.y*smem[(kk*4+1)*32 + b]
                     + w.z*smem[(kk*4+2)*32 + b] + w.w*smem[(kk*4+3)*32 + b];
            }
            #pragma unroll
            for (int ff = 0; ff < 16; ff++) {
                float4 w = wx4[ff];
                acc += w.x*smem[8192 + (ff*4  )*32 + b] + w.y*smem[8192 + (ff*4+1)*32 + b]
                     + w.z*smem[8192 + (ff*4+2)*32 + b] + w.w*smem[8192 + (ff*4+3)*32 + b];
            }
            g_candH[(t*B_ + b)*C_ + c] = fmaxf(acc, 0.f);
        } else if (row == 1728) {                          // beta
            const float4* u4 = (const float4*)uvec;
            float acc = 0.f;
            #pragma unroll 8
            for (int kk = 0; kk < 64; kk++) {
                float4 w = u4[kk];
                acc += w.x*smem[(kk*4  )*32 + b] + w.y*smem[(kk*4+1)*32 + b]
                     + w.z*smem[(kk*4+2)*32 + b] + w.w*smem[(kk*4+3)*32 + b];
            }
            float sp = (acc > 0.f) ? acc + log1pf(expf(-acc)) : log1pf(expf(acc));
            g_beta[b] = sp + 1.f;
        }
    } else if (blk < 63) {
        // ---- q rows (row-per-warp, weights read once) ----
        float4* s4 = (float4*)smem;
        const float4* h4 = (const float4*)g_h;
        for (int i = tid; i < 2048; i += 1024) s4[i] = h4[i];
        __syncthreads();
        int m = (blk - 55)*32 + wl;
        int b = lane;
        const float4* w4 = (const float4*)Wq + m*64;
        float acc = bq[m];
        #pragma unroll 8
        for (int kk = 0; kk < 64; kk++) {
            float4 w = w4[kk];
            acc += w.x*smem[(kk*4  )*32 + b] + w.y*smem[(kk*4+1)*32 + b]
                 + w.z*smem[(kk*4+2)*32 + b] + w.w*smem[(kk*4+3)*32 + b];
        }
        g_q[b*M_ + m] = acc;
    } else {
        if (t > 0) write_out(Wout, bo, out, t - 1, wl, lane);
    }
}

// ================= K2: attention per b (d, sim, softmax, w, G, reading) =====
__global__ __launch_bounds__(1024, 1)
void k_attn(int t)
{
    __shared__ __align__(16) float s_q[M_];
    __shared__ float s_d[32];
    __shared__ __align__(16) float s_w[N_];
    __shared__ float s_m[32];
    __shared__ float s_e[32];
    __shared__ float s_G[32];
    int b = blockIdx.x, tid = threadIdx.x, lane = tid & 31, wl = tid >> 5;

    if (tid < M_) s_q[tid] = g_q[b*M_ + tid];
    __syncthreads();

    // d_s = cand_s[:,b] . q_c   (warp per s)
    if (wl < t) {
        const float* cr = g_candH + (wl*B_ + b)*C_;
        float acc = 0.f;
        #pragma unroll
        for (int j = 0; j < 6; j++) {
            int c = lane + 32*j;
            acc += cr[c] * s_q[A_ + c];
        }
        acc = warp_sum(acc);
        if (lane == 0) s_d[wl] = acc;
    }
    __syncthreads();

    // sim[n] (thread per n, all loads coalesced)
    int n = tid;
    float acc = 0.f;
    #pragma unroll 8
    for (int a = 0; a < A_; a++)
        acc += s_q[a] * g_addrT[a*N_ + n];
    for (int s = 0; s < t; s++)
        acc += g_W2[(s*B_ + b)*N_ + n] * s_d[s];
    float v = g_beta[b] * acc;

    // block softmax
    float m = warp_max(v);
    if (lane == 0) s_m[wl] = m;
    __syncthreads();
    float mb = s_m[0];
    #pragma unroll
    for (int w = 1; w < 32; w++) mb = fmaxf(mb, s_m[w]);
    float e = expf(v - mb);
    float es = warp_sum(e);
    if (lane == 0) s_e[wl] = es;
    __syncthreads();
    float ss = 0.f;
    #pragma unroll
    for (int w = 0; w < 32; w++) ss += s_e[w];
    float wv = e / ss;
    s_w[tid] = wv;
    g_W2[(t*B_ + b)*N_ + tid] = wv;     // coalesced
    __syncthreads();

    // G_s = w_t . w_s (warp per s)
    if (wl < t) {
        const float4* w2 = (const float4*)(g_W2 + (wl*B_ + b)*N_);
        const float4* sw4 = (const float4*)s_w;
        float g = 0.f;
        #pragma unroll
        for (int j = 0; j < 8; j++) {
            float4 a_ = w2[j*32 + lane];
            float4 c_ = sw4[j*32 + lane];
            g += a_.x*c_.x + a_.y*c_.y + a_.z*c_.z + a_.w*c_.w;
        }
        g = warp_sum(g);
        if (lane == 0) s_G[wl] = g;
    }

    // ra[a] = sum_n w[n] * addrT[a][n]  (warp per a; a = wl and wl+32)
    {
        const float* at0 = g_addrT + wl*N_;
        const float* at1 = g_addrT + (wl + 32)*N_;
        float a0 = 0.f, a1 = 0.f;
        #pragma unroll 4
        for (int i = 0; i < 32; i++) {
            int nn = i*32 + lane;
            float wn = s_w[nn];
            a0 += wn * at0[nn];
            a1 += wn * at1[nn];
        }
        a0 = warp_sum(a0);
        a1 = warp_sum(a1);
        if (lane == 0) {
            g_r[wl*32 + b] = a0;
            g_r[(wl + 32)*32 + b] = a1;
        }
    }
    __syncthreads();

    // rc[c] = sum_s G_s * cand_s[c,b]
    if (tid < C_) {
        float acc2 = 0.f;
        for (int s = 0; s < t; s++)
            acc2 += s_G[s] * g_candH[(s*B_ + b)*C_ + tid];
        g_r[(A_ + tid)*32 + b] = acc2;
    }
}

// ================= K3: GRU =================
__global__ __launch_bounds__(1024, 1)
void k_gru(const float* __restrict__ Wm, const float* __restrict__ bm,
           float* __restrict__ out, int t)
{
    int blk = blockIdx.x, tid = threadIdx.x, lane = tid & 31, wl = tid >> 5;
    __shared__ __align__(16) float smem[10240];
    float4* s4 = (float4*)smem;
    const float4* r4 = (const float4*)g_r;
    for (int i = tid; i < 2048; i += 1024) s4[i] = r4[i];
    __syncthreads();
    int p = wl >> 1, kh = wl & 1;
    int hid = blk*16 + p, b = lane;
    const float4* wm4 = (const float4*)Wm;
    float acc0, acc1, acc2;
    if (kh == 0) { acc0 = bm[hid]; acc1 = bm[H_ + hid]; acc2 = bm[2*H_ + hid]; }
    else { acc0 = acc1 = acc2 = 0.f; }
    int mbeg = kh << 5;
    #pragma unroll 4
    for (int mm = mbeg; mm < mbeg + 32; mm++) {
        float r0 = smem[(mm*4  )*32 + b], r1 = smem[(mm*4+1)*32 + b];
        float r2 = smem[(mm*4+2)*32 + b], r3 = smem[(mm*4+3)*32 + b];
        float4 w0 = wm4[hid*64 + mm];
        float4 w1 = wm4[(H_ + hid)*64 + mm];
        float4 w2 = wm4[(2*H_ + hid)*64 + mm];
        acc0 += w0.x*r0 + w0.y*r1 + w0.z*r2 + w0.w*r3;
        acc1 += w1.x*r0 + w1.y*r1 + w1.z*r2 + w1.w*r3;
        acc2 += w2.x*r0 + w2.y*r1 + w2.z*r2 + w2.w*r3;
    }
    float* s_c = smem + 8192;
    if (kh == 1) {
        s_c[(p*3    )*32 + b] = acc0;
        s_c[(p*3 + 1)*32 + b] = acc1;
        s_c[(p*3 + 2)*32 + b] = acc2;
    }
    __syncthreads();
    if (kh == 0) {
        acc0 += s_c[(p*3    )*32 + b];
        acc1 += s_c[(p*3 + 1)*32 + b];
        acc2 += s_c[(p*3 + 2)*32 + b];
        int gb = hid*32 + b;
        float r  = 1.f / (1.f + expf(-(g_gi[gb] + g_gh[gb] + acc0)));
        float z  = 1.f / (1.f + expf(-(g_gi[H_*B_ + gb] + g_gh[H_*B_ + gb] + acc1)));
        float nn = tanhf(g_gi[2*H_*B_ + gb] + acc2 + r * g_gh[2*H_*B_ + gb]);
        float hn = (1.f - z)*nn + z*g_h[gb];
        g_h[gb] = hn;
        out[t*H_*B_ + gb] = hn;
    }
}

// ================= KH: final head =================
__global__ __launch_bounds__(1024, 1)
void k_head(const float* __restrict__ Wout, const float* __restrict__ bo,
            float* __restrict__ out)
{
    int lane = threadIdx.x & 31, wl = threadIdx.x >> 5;
    write_out(Wout, bo, out, T_ - 1, wl, lane);
}

extern "C" void kernel_launch(void* const* d_in, const int* in_sizes, int n_in,
                              void* d_out, int out_size) {
    (void)in_sizes; (void)n_in; (void)out_size;
    const float* batch = (const float*)d_in[0];
    const float* Wi    = (const float*)d_in[1];
    const float* bi    = (const float*)d_in[2];
    const float* Wh    = (const float*)d_in[3];
    const float* bh    = (const float*)d_in[4];
    const float* Wm    = (const float*)d_in[5];
    const float* bm    = (const float*)d_in[6];
    const float* Wout  = (const float*)d_in[7];
    const float* bo    = (const float*)d_in[8];
    const float* addr  = (const float*)d_in[9];
    const float* Wq    = (const float*)d_in[10];
    const float* bq    = (const float*)d_in[11];
    const float* u     = (const float*)d_in[12];
    const float* Wch   = (const float*)d_in[13];
    const float* Wci   = (const float*)d_in[14];
    float* out = (float*)d_out;

    k_init<<<64, 256>>>(batch, addr);
    for (int t = 0; t < T_; t++) {
        k_front<<<64, 1024>>>(Wi, bi, Wh, bh, Wch, Wci, u, Wq, bq, Wout, bo, out, t);
        k_attn<<<32, 1024>>>(t);
        k_gru<<<16, 1024>>>(Wm, bm, out, t);
    }
    k_head<<<1, 1024>>>(Wout, bo, out);
}